// round 15
// baseline (speedup 1.0000x reference)
#include <cuda_runtime.h>
#include <cuda_fp16.h>
#include <math.h>
#include <stdint.h>

#define IN_DIM   256
#define STATE    512
#define OUT_DIM  256
#define NSEQ     32768
#define KY       1280   // x0_re(512) | x0_im(512) | u(256)

// ---------------- device scratch (no allocation allowed), 16B-aligned ----------------
__device__ __align__(16) float g_lam_re[STATE];
__device__ __align__(16) float g_lam_im[STATE];
__device__ __align__(16) float g_gam[STATE];
__device__ __align__(16) float g_G[2 * STATE * IN_DIM];  // [1024,256] fp32 (k_F + c64 fallback)
// fp16 weights — ONLY referenced from device code (host shadow address invalid on ATS)
__device__ __align__(16) __half g_Wy_h[OUT_DIM * KY];     // [256][1280] = [P|Q|F]
__device__ __align__(16) __half g_Ws_h[STATE * IN_DIM];   // [512][256]  = Bn_re

// ---------------- PTX helpers (sm_80-era; legal on compute_103) ----------------
__device__ __forceinline__ uint32_t smem_u32(const void* p) {
    uint32_t a;
    asm("{ .reg .u64 t; cvta.to.shared.u64 t, %1; cvt.u32.u64 %0, t; }" : "=r"(a) : "l"(p));
    return a;
}
__device__ __forceinline__ void sts128(uint32_t a, uint32_t x, uint32_t y, uint32_t z, uint32_t w) {
    asm volatile("st.shared.v4.b32 [%0], {%1,%2,%3,%4};" :: "r"(a), "r"(x), "r"(y), "r"(z), "r"(w) : "memory");
}
__device__ __forceinline__ void cp16(uint32_t dst, const void* src) {
    asm volatile("cp.async.cg.shared.global [%0], [%1], 16;" :: "r"(dst), "l"(src) : "memory");
}
__device__ __forceinline__ void cp_commit_wait() {
    asm volatile("cp.async.commit_group;" ::: "memory");
    asm volatile("cp.async.wait_group 0;" ::: "memory");
}
__device__ __forceinline__ void ldm_x4(uint32_t* r, uint32_t addr) {
    asm volatile("ldmatrix.sync.aligned.m8n8.x4.shared.b16 {%0,%1,%2,%3}, [%4];"
        : "=r"(r[0]), "=r"(r[1]), "=r"(r[2]), "=r"(r[3]) : "r"(addr));
}
__device__ __forceinline__ void mma_f16(float* c, const uint32_t* a, const uint32_t* b) {
    asm volatile(
        "mma.sync.aligned.m16n8k16.row.col.f32.f16.f16.f32 "
        "{%0,%1,%2,%3}, {%4,%5,%6,%7}, {%8,%9}, {%0,%1,%2,%3};"
        : "+f"(c[0]), "+f"(c[1]), "+f"(c[2]), "+f"(c[3])
        : "r"(a[0]), "r"(a[1]), "r"(a[2]), "r"(a[3]), "r"(b[0]), "r"(b[1]));
}

// ---------------- precompute (3 launches) ----------------
__global__ void k_lam(const float* __restrict__ nu_log,
                      const float* __restrict__ theta_log,
                      const float* __restrict__ gamma_log) {
    int h = threadIdx.x;
    float mod = expf(-expf(nu_log[h]));
    float th  = expf(theta_log[h]);
    g_lam_re[h] = mod * cosf(th);
    g_lam_im[h] = mod * sinf(th);
    g_gam[h]    = expf(gamma_log[h]);
}

__global__ void k_weights(const float* __restrict__ B_re, const float* __restrict__ B_im,
                          const float* __restrict__ C_re, const float* __restrict__ C_im) {
    int idx = blockIdx.x * blockDim.x + threadIdx.x;
    const int NG = 2 * STATE * IN_DIM;
    const int NP = OUT_DIM * STATE;
    if (idx < NG) {
        int c = idx / IN_DIM, j = idx % IN_DIM, h = c >> 1;
        float b = (c & 1) ? B_im[h * IN_DIM + j] : B_re[h * IN_DIM + j];
        float v = b * g_gam[h];
        g_G[idx] = v;
        if (!(c & 1))
            g_Ws_h[h * IN_DIM + j] = __float2half(v);
    } else if (idx < NG + NP) {
        int t = idx - NG;
        int o = t / STATE, h = t % STATE;
        float cr = C_re[o * STATE + h], ci = C_im[o * STATE + h];
        float lr = g_lam_re[h], li = g_lam_im[h];
        g_Wy_h[o * KY + h]       = __float2half(lr * cr - li * ci);
        g_Wy_h[o * KY + 512 + h] = __float2half(-(li * cr + lr * ci));
    }
}

__global__ void k_F(const float* __restrict__ C_re, const float* __restrict__ C_im,
                    const float* __restrict__ D) {
    __shared__ float sCr[16][16], sCi[16][16], sGr[16][17], sGi[16][17];
    int o0 = blockIdx.y * 16, j0 = blockIdx.x * 16;
    int tx = threadIdx.x, ty = threadIdx.y;
    float acc = 0.f;
    for (int h0 = 0; h0 < STATE; h0 += 16) {
        sCr[ty][tx] = C_re[(o0 + ty) * STATE + h0 + tx];
        sCi[ty][tx] = C_im[(o0 + ty) * STATE + h0 + tx];
        sGr[ty][tx] = g_G[(2 * (h0 + ty)) * IN_DIM + j0 + tx];
        sGi[ty][tx] = g_G[(2 * (h0 + ty) + 1) * IN_DIM + j0 + tx];
        __syncthreads();
#pragma unroll
        for (int k = 0; k < 16; k++)
            acc += sCr[ty][k] * sGr[k][tx] - sCi[ty][k] * sGi[k][tx];
        __syncthreads();
    }
    float fv = D[(o0 + ty) * IN_DIM + j0 + tx] + acc;
    g_Wy_h[(o0 + ty) * KY + 1024 + j0 + tx] = __float2half(fv);
}

// ---------------- merged pipelined mma.sync GEMM (fp16, 2-term A split) ----------------
// BM=128, BN=128, BK=32, 512 thr (16 warps), 1 CTA/SM. N-inner block map (L2 reuse of A).
//   y blocks   [0, 512):    m = t>>1, n = t&1   (K=1280)
//   s blocks   [512, 1536): m = t>>2, n = t&3   (K=256, epilogue Re(lam*x0), clamped)
// Warps: 4 over M x 4 over N, warp tile 32x32 (mt=2, nt=4), 2 MMAs per (mt,nt) per k16.
#define NY_BLK 512
#define NS_BLK 1024
#define A_HI_B 0
#define A_LO_B 10240
#define W_B    20480
#define STG_B  30720
#define SMEM_BYTES (2 * STG_B)   // 61440

__global__ __launch_bounds__(512, 1)
void k_merged(const float* __restrict__ u, const float* __restrict__ x0_re,
              const float* __restrict__ x0_im, float* __restrict__ out, long long lim) {
    extern __shared__ __half sm[];
    uint32_t sb = smem_u32(sm);

    int bid = blockIdx.x;
    bool is_y = bid < NY_BLK;
    int t_ = is_y ? bid : bid - NY_BLK;
    int m0, n0;
    if (is_y) { m0 = (t_ >> 1) * 128; n0 = (t_ & 1) * 128; }
    else      { m0 = (t_ >> 2) * 128; n0 = (t_ & 3) * 128; }
    int KT = is_y ? KY : IN_DIM;
    const __half* __restrict__ Wp = is_y ? g_Wy_h : g_Ws_h;

    int tid  = threadIdx.x;
    int wid  = tid >> 5;
    int lane = tid & 31;
    int wm = wid & 3;          // 4 warps over M (32 rows each)
    int wn = wid >> 2;         // 4 warps over N (32 cols each)

    float acc[2][4][4];
#pragma unroll
    for (int i = 0; i < 2; i++)
#pragma unroll
        for (int j = 0; j < 4; j++)
#pragma unroll
            for (int q = 0; q < 4; q++) acc[i][j][q] = 0.f;

    int lr_ = tid >> 2;         // loader row (0..127) for BOTH A and W
    int lq  = tid & 3;          // k-quarter (8 elems)
    uint32_t lbase = (uint32_t)lr_ * 80 + lq * 16;

    auto a_ptr = [&](int k0) -> const float* {
        const float* Ag; int astr;
        if (is_y) {
            if (k0 < 512)       { Ag = x0_re + k0;          astr = STATE; }
            else if (k0 < 1024) { Ag = x0_im + (k0 - 512);  astr = STATE; }
            else                { Ag = u + (k0 - 1024);     astr = IN_DIM; }
        } else { Ag = u + k0; astr = IN_DIM; }
        return Ag + (size_t)(m0 + lr_) * astr + lq * 8;
    };

    float4 pv0, pv1;            // 8 fp32 A prefetch values per thread
    auto load_a = [&](int k0) {
        const float* p = a_ptr(k0);
        pv0 = *(const float4*)(p);
        pv1 = *(const float4*)(p + 4);
    };
    auto issue_w = [&](int k0, uint32_t stgB) {
        size_t off = (size_t)(n0 + lr_) * KT + k0 + lq * 8;
        cp16(sb + stgB + W_B + lbase, Wp + off);
    };
    auto store_a = [&](uint32_t stgB) {
        float xs[8] = {pv0.x, pv0.y, pv0.z, pv0.w, pv1.x, pv1.y, pv1.z, pv1.w};
        uint32_t hu[4], lu[4];
#pragma unroll
        for (int q = 0; q < 4; q++) {
            __half h0 = __float2half(xs[2 * q]);
            __half h1 = __float2half(xs[2 * q + 1]);
            uint32_t l0 = (uint32_t)__half_as_ushort(__float2half(xs[2 * q]     - __half2float(h0)));
            uint32_t l1 = (uint32_t)__half_as_ushort(__float2half(xs[2 * q + 1] - __half2float(h1)));
            hu[q] = (uint32_t)__half_as_ushort(h0) | ((uint32_t)__half_as_ushort(h1) << 16);
            lu[q] = l0 | (l1 << 16);
        }
        uint32_t b = sb + stgB + lbase;
        sts128(b + A_HI_B, hu[0], hu[1], hu[2], hu[3]);
        sts128(b + A_LO_B, lu[0], lu[1], lu[2], lu[3]);
    };

    // prologue
    load_a(0);
    issue_w(0, 0);
    store_a(0);
    cp_commit_wait();
    __syncthreads();

#pragma unroll 1
    for (int k0 = 0; k0 < KT; k0 += 32) {
        uint32_t cur = (uint32_t)((k0 >> 5) & 1) * STG_B;
        uint32_t nxt = STG_B - cur;
        bool more = (k0 + 32) < KT;
        if (more) { load_a(k0 + 32); issue_w(k0 + 32, nxt); }

        uint32_t sc = sb + cur;
#pragma unroll
        for (int ks = 0; ks < 2; ks++) {
            uint32_t ah[2][4], al[2][4], bh[4][2];
            uint32_t acol = ks * 32 + (lane >> 4) * 16;
#pragma unroll
            for (int mt = 0; mt < 2; mt++) {
                uint32_t r = wm * 32 + mt * 16 + (lane & 15);
                uint32_t ad = r * 80 + acol;
                ldm_x4(ah[mt], sc + A_HI_B + ad);
                ldm_x4(al[mt], sc + A_LO_B + ad);
            }
            // W fragments: paired x4 — one call covers two n-subtiles (16 rows x 16 k)
            uint32_t brow_lo = (uint32_t)((lane >> 4) << 3) + (lane & 7);
            uint32_t bcol    = ks * 32 + ((lane >> 3) & 1) * 16;
#pragma unroll
            for (int p = 0; p < 2; p++) {
                uint32_t n = wn * 32 + p * 16 + brow_lo;
                uint32_t bd = n * 80 + bcol;
                uint32_t th[4];
                ldm_x4(th, sc + W_B + bd);
                bh[2*p][0] = th[0]; bh[2*p][1] = th[1];
                bh[2*p+1][0] = th[2]; bh[2*p+1][1] = th[3];
            }
#pragma unroll
            for (int mt = 0; mt < 2; mt++)
#pragma unroll
                for (int nt = 0; nt < 4; nt++) {
                    mma_f16(acc[mt][nt], ah[mt], bh[nt]);
                    mma_f16(acc[mt][nt], al[mt], bh[nt]);
                }
        }

        if (more) { store_a(nxt); cp_commit_wait(); }
        __syncthreads();
    }

    // epilogue
    int rbase = m0 + wm * 32 + (lane >> 2);
    int cbase = n0 + wn * 32 + 2 * (lane & 3);
#pragma unroll
    for (int mt = 0; mt < 2; mt++) {
#pragma unroll
        for (int nt = 0; nt < 4; nt++) {
            int col = cbase + nt * 8;
#pragma unroll
            for (int hrow = 0; hrow < 2; hrow++) {
                int row = rbase + mt * 16 + hrow * 8;
                float v0 = acc[mt][nt][2 * hrow];
                float v1 = acc[mt][nt][2 * hrow + 1];
                if (is_y) {
                    *(float2*)(out + (size_t)row * OUT_DIM + col) = make_float2(v0, v1);
                } else {
                    long long idx = (long long)NSEQ * OUT_DIM + (long long)row * STATE + col;
                    if (idx + 1 < lim) {
                        float2 lr2 = *(const float2*)&g_lam_re[col];
                        float2 li2 = *(const float2*)&g_lam_im[col];
                        float2 xr  = *(const float2*)&x0_re[(size_t)row * STATE + col];
                        float2 xi  = *(const float2*)&x0_im[(size_t)row * STATE + col];
                        float2 o2;
                        o2.x = lr2.x * xr.x - li2.x * xi.x + v0;
                        o2.y = lr2.y * xr.y - li2.y * xi.y + v1;
                        *(float2*)(out + idx) = o2;
                    }
                }
            }
        }
    }
}

// ---------------- legacy fp32 GEMM (interleaved-c64 state fallback only) ----------------
__global__ __launch_bounds__(256)
void k_gemm_c64(const float* __restrict__ A0, int K0,
                const float* __restrict__ x0_re, const float* __restrict__ x0_im,
                float* __restrict__ out, long long lim) {
    const int BM = 128, BN = 64, BK = 16;
    __shared__ float As[BK][BM + 4];
    __shared__ float Bs[BK][BN + 4];
    int tid = threadIdx.x;
    int m0 = blockIdx.x * BM;
    int n0 = blockIdx.y * BN;
    int tx = tid & 15, ty = tid >> 4;
    float acc[8][4];
#pragma unroll
    for (int i = 0; i < 8; i++)
#pragma unroll
        for (int j = 0; j < 4; j++) acc[i][j] = 0.f;
#pragma unroll 1
    for (int k0 = 0; k0 < K0; k0 += BK) {
#pragma unroll
        for (int l = 0; l < 2; l++) {
            int f = tid + l * 256;
            int r = f >> 2, kk4 = (f & 3) * 4;
            float4 v = *(const float4*)&A0[(size_t)(m0 + r) * K0 + k0 + kk4];
            As[kk4 + 0][r] = v.x; As[kk4 + 1][r] = v.y;
            As[kk4 + 2][r] = v.z; As[kk4 + 3][r] = v.w;
        }
        {
            int n = tid >> 2, kk4 = (tid & 3) * 4;
            float4 v = *(const float4*)&g_G[(size_t)(n0 + n) * K0 + k0 + kk4];
            Bs[kk4 + 0][n] = v.x; Bs[kk4 + 1][n] = v.y;
            Bs[kk4 + 2][n] = v.z; Bs[kk4 + 3][n] = v.w;
        }
        __syncthreads();
#pragma unroll
        for (int kk = 0; kk < BK; kk++) {
            float4 b  = *(const float4*)&Bs[kk][tx * 4];
            float4 a0 = *(const float4*)&As[kk][ty * 8];
            float4 a1 = *(const float4*)&As[kk][ty * 8 + 4];
            float av[8] = {a0.x, a0.y, a0.z, a0.w, a1.x, a1.y, a1.z, a1.w};
            float bv[4] = {b.x, b.y, b.z, b.w};
#pragma unroll
            for (int i = 0; i < 8; i++)
#pragma unroll
                for (int j = 0; j < 4; j++) acc[i][j] += av[i] * bv[j];
        }
        __syncthreads();
    }
    int c0 = n0 + tx * 4;
    int h0 = c0 >> 1;
    float lr0 = g_lam_re[h0],     li0 = g_lam_im[h0];
    float lr1 = g_lam_re[h0 + 1], li1 = g_lam_im[h0 + 1];
#pragma unroll
    for (int i = 0; i < 8; i++) {
        int row = m0 + ty * 8 + i;
        long long idx = (long long)row * (2 * STATE) + c0;
        if (idx + 3 < lim) {
            float xr0 = x0_re[(size_t)row * STATE + h0];
            float xi0 = x0_im[(size_t)row * STATE + h0];
            float xr1 = x0_re[(size_t)row * STATE + h0 + 1];
            float xi1 = x0_im[(size_t)row * STATE + h0 + 1];
            float4 v;
            v.x = lr0 * xr0 - li0 * xi0 + acc[i][0];
            v.y = lr0 * xi0 + li0 * xr0 + acc[i][1];
            v.z = lr1 * xr1 - li1 * xi1 + acc[i][2];
            v.w = lr1 * xi1 + li1 * xr1 + acc[i][3];
            *(float4*)&out[idx] = v;
        }
    }
}

// ---------------- launch ----------------
extern "C" void kernel_launch(void* const* d_in, const int* in_sizes, int n_in,
                              void* d_out, int out_size) {
    const long long expect[11] = {
        (long long)NSEQ * IN_DIM, (long long)NSEQ * STATE, (long long)NSEQ * STATE,
        STATE, STATE, STATE,
        (long long)STATE * IN_DIM, (long long)STATE * IN_DIM,
        (long long)OUT_DIM * STATE, (long long)OUT_DIM * STATE,
        (long long)OUT_DIM * IN_DIM
    };
    const float* ptr[11];
    bool used[32] = {false};
    for (int e = 0; e < 11; e++) {
        ptr[e] = nullptr;
        for (int i = 0; i < n_in; i++) {
            if (!used[i] && (long long)in_sizes[i] == expect[e]) {
                ptr[e] = (const float*)d_in[i];
                used[i] = true;
                break;
            }
        }
        if (!ptr[e]) ptr[e] = (const float*)d_in[e < n_in ? e : 0];
    }
    const float* u         = ptr[0];
    const float* x0_re     = ptr[1];
    const float* x0_im     = ptr[2];
    const float* nu_log    = ptr[3];
    const float* theta_log = ptr[4];
    const float* gamma_log = ptr[5];
    const float* B_re      = ptr[6];
    const float* B_im      = ptr[7];
    const float* C_re      = ptr[8];
    const float* C_im      = ptr[9];
    const float* D         = ptr[10];
    float* out = (float*)d_out;

    static int attr_done = 0;
    if (!attr_done) {
        cudaFuncSetAttribute(k_merged, cudaFuncAttributeMaxDynamicSharedMemorySize, SMEM_BYTES);
        attr_done = 1;
    }

    k_lam<<<1, STATE>>>(nu_log, theta_log, gamma_log);
    int tot = 2 * STATE * IN_DIM + OUT_DIM * STATE;
    k_weights<<<(tot + 255) / 256, 256>>>(B_re, B_im, C_re, C_im);
    k_F<<<dim3(IN_DIM / 16, OUT_DIM / 16), dim3(16, 16)>>>(C_re, C_im, D);

    const long long Y_ELEMS      = (long long)NSEQ * OUT_DIM;   //  8,388,608
    const long long ST_C64_ELEMS = (long long)NSEQ * 2 * STATE; // 33,554,432
    long long cap = (long long)out_size;
    if (cap == Y_ELEMS / 2 + ST_C64_ELEMS / 2) cap *= 2;        // c64-counted case
    long long rem = cap - Y_ELEMS;

    if (rem >= ST_C64_ELEMS) {
        k_merged<<<NY_BLK, 512, SMEM_BYTES>>>(u, x0_re, x0_im, out, cap);
        k_gemm_c64<<<dim3(NSEQ / 128, (2 * STATE) / 64), 256>>>(
            u, IN_DIM, x0_re, x0_im, out + Y_ELEMS, rem);
    } else {
        k_merged<<<NY_BLK + NS_BLK, 512, SMEM_BYTES>>>(u, x0_re, x0_im, out, cap);
    }
}

// round 16
// speedup vs baseline: 1.0005x; 1.0005x over previous
#include <cuda_runtime.h>
#include <cuda_fp16.h>
#include <math.h>
#include <stdint.h>

#define IN_DIM   256
#define STATE    512
#define OUT_DIM  256
#define NSEQ     32768
#define KY       1280   // x0_re(512) | x0_im(512) | u(256)

// ---------------- device scratch (no allocation allowed), 16B-aligned ----------------
__device__ __align__(16) float g_lam_re[STATE];
__device__ __align__(16) float g_lam_im[STATE];
__device__ __align__(16) float g_gam[STATE];
__device__ __align__(16) float g_G[2 * STATE * IN_DIM];  // [1024,256] fp32 (k_F + c64 fallback)
// fp16 weights — ONLY referenced from device code (host shadow address invalid on ATS)
__device__ __align__(16) __half g_Wy_h[OUT_DIM * KY];     // [256][1280] = [P|Q|F]
__device__ __align__(16) __half g_Ws_h[STATE * IN_DIM];   // [512][256]  = Bn_re

// ---------------- PTX helpers (sm_80-era; legal on compute_103) ----------------
__device__ __forceinline__ uint32_t smem_u32(const void* p) {
    uint32_t a;
    asm("{ .reg .u64 t; cvta.to.shared.u64 t, %1; cvt.u32.u64 %0, t; }" : "=r"(a) : "l"(p));
    return a;
}
__device__ __forceinline__ void sts128(uint32_t a, uint32_t x, uint32_t y, uint32_t z, uint32_t w) {
    asm volatile("st.shared.v4.b32 [%0], {%1,%2,%3,%4};" :: "r"(a), "r"(x), "r"(y), "r"(z), "r"(w) : "memory");
}
__device__ __forceinline__ void cp16(uint32_t dst, const void* src) {
    asm volatile("cp.async.cg.shared.global [%0], [%1], 16;" :: "r"(dst), "l"(src) : "memory");
}
__device__ __forceinline__ void cp_commit_wait() {
    asm volatile("cp.async.commit_group;" ::: "memory");
    asm volatile("cp.async.wait_group 0;" ::: "memory");
}
__device__ __forceinline__ void ldm_x4(uint32_t* r, uint32_t addr) {
    asm volatile("ldmatrix.sync.aligned.m8n8.x4.shared.b16 {%0,%1,%2,%3}, [%4];"
        : "=r"(r[0]), "=r"(r[1]), "=r"(r[2]), "=r"(r[3]) : "r"(addr));
}
__device__ __forceinline__ void mma_f16(float* c, const uint32_t* a, const uint32_t* b) {
    asm volatile(
        "mma.sync.aligned.m16n8k16.row.col.f32.f16.f16.f32 "
        "{%0,%1,%2,%3}, {%4,%5,%6,%7}, {%8,%9}, {%0,%1,%2,%3};"
        : "+f"(c[0]), "+f"(c[1]), "+f"(c[2]), "+f"(c[3])
        : "r"(a[0]), "r"(a[1]), "r"(a[2]), "r"(a[3]), "r"(b[0]), "r"(b[1]));
}

// ---------------- precompute (3 launches) ----------------
__global__ void k_lam(const float* __restrict__ nu_log,
                      const float* __restrict__ theta_log,
                      const float* __restrict__ gamma_log) {
    int h = threadIdx.x;
    float mod = expf(-expf(nu_log[h]));
    float th  = expf(theta_log[h]);
    g_lam_re[h] = mod * cosf(th);
    g_lam_im[h] = mod * sinf(th);
    g_gam[h]    = expf(gamma_log[h]);
}

__global__ void k_weights(const float* __restrict__ B_re, const float* __restrict__ B_im,
                          const float* __restrict__ C_re, const float* __restrict__ C_im) {
    int idx = blockIdx.x * blockDim.x + threadIdx.x;
    const int NG = 2 * STATE * IN_DIM;
    const int NP = OUT_DIM * STATE;
    if (idx < NG) {
        int c = idx / IN_DIM, j = idx % IN_DIM, h = c >> 1;
        float b = (c & 1) ? B_im[h * IN_DIM + j] : B_re[h * IN_DIM + j];
        float v = b * g_gam[h];
        g_G[idx] = v;
        if (!(c & 1))
            g_Ws_h[h * IN_DIM + j] = __float2half(v);
    } else if (idx < NG + NP) {
        int t = idx - NG;
        int o = t / STATE, h = t % STATE;
        float cr = C_re[o * STATE + h], ci = C_im[o * STATE + h];
        float lr = g_lam_re[h], li = g_lam_im[h];
        g_Wy_h[o * KY + h]       = __float2half(lr * cr - li * ci);
        g_Wy_h[o * KY + 512 + h] = __float2half(-(li * cr + lr * ci));
    }
}

__global__ void k_F(const float* __restrict__ C_re, const float* __restrict__ C_im,
                    const float* __restrict__ D) {
    __shared__ float sCr[16][16], sCi[16][16], sGr[16][17], sGi[16][17];
    int o0 = blockIdx.y * 16, j0 = blockIdx.x * 16;
    int tx = threadIdx.x, ty = threadIdx.y;
    float acc = 0.f;
    for (int h0 = 0; h0 < STATE; h0 += 16) {
        sCr[ty][tx] = C_re[(o0 + ty) * STATE + h0 + tx];
        sCi[ty][tx] = C_im[(o0 + ty) * STATE + h0 + tx];
        sGr[ty][tx] = g_G[(2 * (h0 + ty)) * IN_DIM + j0 + tx];
        sGi[ty][tx] = g_G[(2 * (h0 + ty) + 1) * IN_DIM + j0 + tx];
        __syncthreads();
#pragma unroll
        for (int k = 0; k < 16; k++)
            acc += sCr[ty][k] * sGr[k][tx] - sCi[ty][k] * sGi[k][tx];
        __syncthreads();
    }
    float fv = D[(o0 + ty) * IN_DIM + j0 + tx] + acc;
    g_Wy_h[(o0 + ty) * KY + 1024 + j0 + tx] = __float2half(fv);
}

// ---------------- merged pipelined mma.sync GEMM (fp16, 2-term A split) ----------------
// BM=128, BN=128, BK=32, 512 thr (16 warps), 1 CTA/SM. N-inner block map (L2 reuse of A).
//   y blocks   [0, 512):    m = t>>1, n = t&1   (K=1280)
//   s blocks   [512, 1536): m = t>>2, n = t&3   (K=256, epilogue Re(lam*x0), clamped)
// Warps: 4 over M x 4 over N, warp tile 32x32 (mt=2, nt=4), 2 MMAs per (mt,nt) per k16.
#define NY_BLK 512
#define NS_BLK 1024
#define A_HI_B 0
#define A_LO_B 10240
#define W_B    20480
#define STG_B  30720
#define SMEM_BYTES (2 * STG_B)   // 61440

__global__ __launch_bounds__(512, 1)
void k_merged(const float* __restrict__ u, const float* __restrict__ x0_re,
              const float* __restrict__ x0_im, float* __restrict__ out, long long lim) {
    extern __shared__ __half sm[];
    uint32_t sb = smem_u32(sm);

    int bid = blockIdx.x;
    bool is_y = bid < NY_BLK;
    int t_ = is_y ? bid : bid - NY_BLK;
    int m0, n0;
    if (is_y) { m0 = (t_ >> 1) * 128; n0 = (t_ & 1) * 128; }
    else      { m0 = (t_ >> 2) * 128; n0 = (t_ & 3) * 128; }
    int KT = is_y ? KY : IN_DIM;
    const __half* __restrict__ Wp = is_y ? g_Wy_h : g_Ws_h;

    int tid  = threadIdx.x;
    int wid  = tid >> 5;
    int lane = tid & 31;
    int wm = wid & 3;          // 4 warps over M (32 rows each)
    int wn = wid >> 2;         // 4 warps over N (32 cols each)

    float acc[2][4][4];
#pragma unroll
    for (int i = 0; i < 2; i++)
#pragma unroll
        for (int j = 0; j < 4; j++)
#pragma unroll
            for (int q = 0; q < 4; q++) acc[i][j][q] = 0.f;

    int lr_ = tid >> 2;         // loader row (0..127) for BOTH A and W
    int lq  = tid & 3;          // k-quarter (8 elems)
    uint32_t lbase = (uint32_t)lr_ * 80 + lq * 16;

    auto a_ptr = [&](int k0) -> const float* {
        const float* Ag; int astr;
        if (is_y) {
            if (k0 < 512)       { Ag = x0_re + k0;          astr = STATE; }
            else if (k0 < 1024) { Ag = x0_im + (k0 - 512);  astr = STATE; }
            else                { Ag = u + (k0 - 1024);     astr = IN_DIM; }
        } else { Ag = u + k0; astr = IN_DIM; }
        return Ag + (size_t)(m0 + lr_) * astr + lq * 8;
    };

    float4 pv0, pv1;            // 8 fp32 A prefetch values per thread
    auto load_a = [&](int k0) {
        const float* p = a_ptr(k0);
        pv0 = *(const float4*)(p);
        pv1 = *(const float4*)(p + 4);
    };
    auto issue_w = [&](int k0, uint32_t stgB) {
        size_t off = (size_t)(n0 + lr_) * KT + k0 + lq * 8;
        cp16(sb + stgB + W_B + lbase, Wp + off);
    };
    auto store_a = [&](uint32_t stgB) {
        float xs[8] = {pv0.x, pv0.y, pv0.z, pv0.w, pv1.x, pv1.y, pv1.z, pv1.w};
        uint32_t hu[4], lu[4];
#pragma unroll
        for (int q = 0; q < 4; q++) {
            __half h0 = __float2half(xs[2 * q]);
            __half h1 = __float2half(xs[2 * q + 1]);
            uint32_t l0 = (uint32_t)__half_as_ushort(__float2half(xs[2 * q]     - __half2float(h0)));
            uint32_t l1 = (uint32_t)__half_as_ushort(__float2half(xs[2 * q + 1] - __half2float(h1)));
            hu[q] = (uint32_t)__half_as_ushort(h0) | ((uint32_t)__half_as_ushort(h1) << 16);
            lu[q] = l0 | (l1 << 16);
        }
        uint32_t b = sb + stgB + lbase;
        sts128(b + A_HI_B, hu[0], hu[1], hu[2], hu[3]);
        sts128(b + A_LO_B, lu[0], lu[1], lu[2], lu[3]);
    };

    // prologue
    load_a(0);
    issue_w(0, 0);
    store_a(0);
    cp_commit_wait();
    __syncthreads();

#pragma unroll 1
    for (int k0 = 0; k0 < KT; k0 += 32) {
        uint32_t cur = (uint32_t)((k0 >> 5) & 1) * STG_B;
        uint32_t nxt = STG_B - cur;
        bool more = (k0 + 32) < KT;
        if (more) { load_a(k0 + 32); issue_w(k0 + 32, nxt); }

        uint32_t sc = sb + cur;
#pragma unroll
        for (int ks = 0; ks < 2; ks++) {
            uint32_t ah[2][4], al[2][4], bh[4][2];
            uint32_t acol = ks * 32 + (lane >> 4) * 16;
#pragma unroll
            for (int mt = 0; mt < 2; mt++) {
                uint32_t r = wm * 32 + mt * 16 + (lane & 15);
                uint32_t ad = r * 80 + acol;
                ldm_x4(ah[mt], sc + A_HI_B + ad);
                ldm_x4(al[mt], sc + A_LO_B + ad);
            }
            // W fragments: paired x4 — one call covers two n-subtiles (16 rows x 16 k)
            uint32_t brow_lo = (uint32_t)((lane >> 4) << 3) + (lane & 7);
            uint32_t bcol    = ks * 32 + ((lane >> 3) & 1) * 16;
#pragma unroll
            for (int p = 0; p < 2; p++) {
                uint32_t n = wn * 32 + p * 16 + brow_lo;
                uint32_t bd = n * 80 + bcol;
                uint32_t th[4];
                ldm_x4(th, sc + W_B + bd);
                bh[2*p][0] = th[0]; bh[2*p][1] = th[1];
                bh[2*p+1][0] = th[2]; bh[2*p+1][1] = th[3];
            }
#pragma unroll
            for (int mt = 0; mt < 2; mt++)
#pragma unroll
                for (int nt = 0; nt < 4; nt++) {
                    mma_f16(acc[mt][nt], ah[mt], bh[nt]);
                    mma_f16(acc[mt][nt], al[mt], bh[nt]);
                }
        }

        if (more) { store_a(nxt); cp_commit_wait(); }
        __syncthreads();
    }

    // epilogue
    int rbase = m0 + wm * 32 + (lane >> 2);
    int cbase = n0 + wn * 32 + 2 * (lane & 3);
#pragma unroll
    for (int mt = 0; mt < 2; mt++) {
#pragma unroll
        for (int nt = 0; nt < 4; nt++) {
            int col = cbase + nt * 8;
#pragma unroll
            for (int hrow = 0; hrow < 2; hrow++) {
                int row = rbase + mt * 16 + hrow * 8;
                float v0 = acc[mt][nt][2 * hrow];
                float v1 = acc[mt][nt][2 * hrow + 1];
                if (is_y) {
                    *(float2*)(out + (size_t)row * OUT_DIM + col) = make_float2(v0, v1);
                } else {
                    long long idx = (long long)NSEQ * OUT_DIM + (long long)row * STATE + col;
                    if (idx + 1 < lim) {
                        float2 lr2 = *(const float2*)&g_lam_re[col];
                        float2 li2 = *(const float2*)&g_lam_im[col];
                        float2 xr  = *(const float2*)&x0_re[(size_t)row * STATE + col];
                        float2 xi  = *(const float2*)&x0_im[(size_t)row * STATE + col];
                        float2 o2;
                        o2.x = lr2.x * xr.x - li2.x * xi.x + v0;
                        o2.y = lr2.y * xr.y - li2.y * xi.y + v1;
                        *(float2*)(out + idx) = o2;
                    }
                }
            }
        }
    }
}

// ---------------- legacy fp32 GEMM (interleaved-c64 state fallback only) ----------------
__global__ __launch_bounds__(256)
void k_gemm_c64(const float* __restrict__ A0, int K0,
                const float* __restrict__ x0_re, const float* __restrict__ x0_im,
                float* __restrict__ out, long long lim) {
    const int BM = 128, BN = 64, BK = 16;
    __shared__ float As[BK][BM + 4];
    __shared__ float Bs[BK][BN + 4];
    int tid = threadIdx.x;
    int m0 = blockIdx.x * BM;
    int n0 = blockIdx.y * BN;
    int tx = tid & 15, ty = tid >> 4;
    float acc[8][4];
#pragma unroll
    for (int i = 0; i < 8; i++)
#pragma unroll
        for (int j = 0; j < 4; j++) acc[i][j] = 0.f;
#pragma unroll 1
    for (int k0 = 0; k0 < K0; k0 += BK) {
#pragma unroll
        for (int l = 0; l < 2; l++) {
            int f = tid + l * 256;
            int r = f >> 2, kk4 = (f & 3) * 4;
            float4 v = *(const float4*)&A0[(size_t)(m0 + r) * K0 + k0 + kk4];
            As[kk4 + 0][r] = v.x; As[kk4 + 1][r] = v.y;
            As[kk4 + 2][r] = v.z; As[kk4 + 3][r] = v.w;
        }
        {
            int n = tid >> 2, kk4 = (tid & 3) * 4;
            float4 v = *(const float4*)&g_G[(size_t)(n0 + n) * K0 + k0 + kk4];
            Bs[kk4 + 0][n] = v.x; Bs[kk4 + 1][n] = v.y;
            Bs[kk4 + 2][n] = v.z; Bs[kk4 + 3][n] = v.w;
        }
        __syncthreads();
#pragma unroll
        for (int kk = 0; kk < BK; kk++) {
            float4 b  = *(const float4*)&Bs[kk][tx * 4];
            float4 a0 = *(const float4*)&As[kk][ty * 8];
            float4 a1 = *(const float4*)&As[kk][ty * 8 + 4];
            float av[8] = {a0.x, a0.y, a0.z, a0.w, a1.x, a1.y, a1.z, a1.w};
            float bv[4] = {b.x, b.y, b.z, b.w};
#pragma unroll
            for (int i = 0; i < 8; i++)
#pragma unroll
                for (int j = 0; j < 4; j++) acc[i][j] += av[i] * bv[j];
        }
        __syncthreads();
    }
    int c0 = n0 + tx * 4;
    int h0 = c0 >> 1;
    float lr0 = g_lam_re[h0],     li0 = g_lam_im[h0];
    float lr1 = g_lam_re[h0 + 1], li1 = g_lam_im[h0 + 1];
#pragma unroll
    for (int i = 0; i < 8; i++) {
        int row = m0 + ty * 8 + i;
        long long idx = (long long)row * (2 * STATE) + c0;
        if (idx + 3 < lim) {
            float xr0 = x0_re[(size_t)row * STATE + h0];
            float xi0 = x0_im[(size_t)row * STATE + h0];
            float xr1 = x0_re[(size_t)row * STATE + h0 + 1];
            float xi1 = x0_im[(size_t)row * STATE + h0 + 1];
            float4 v;
            v.x = lr0 * xr0 - li0 * xi0 + acc[i][0];
            v.y = lr0 * xi0 + li0 * xr0 + acc[i][1];
            v.z = lr1 * xr1 - li1 * xi1 + acc[i][2];
            v.w = lr1 * xi1 + li1 * xr1 + acc[i][3];
            *(float4*)&out[idx] = v;
        }
    }
}

// ---------------- launch ----------------
extern "C" void kernel_launch(void* const* d_in, const int* in_sizes, int n_in,
                              void* d_out, int out_size) {
    const long long expect[11] = {
        (long long)NSEQ * IN_DIM, (long long)NSEQ * STATE, (long long)NSEQ * STATE,
        STATE, STATE, STATE,
        (long long)STATE * IN_DIM, (long long)STATE * IN_DIM,
        (long long)OUT_DIM * STATE, (long long)OUT_DIM * STATE,
        (long long)OUT_DIM * IN_DIM
    };
    const float* ptr[11];
    bool used[32] = {false};
    for (int e = 0; e < 11; e++) {
        ptr[e] = nullptr;
        for (int i = 0; i < n_in; i++) {
            if (!used[i] && (long long)in_sizes[i] == expect[e]) {
                ptr[e] = (const float*)d_in[i];
                used[i] = true;
                break;
            }
        }
        if (!ptr[e]) ptr[e] = (const float*)d_in[e < n_in ? e : 0];
    }
    const float* u         = ptr[0];
    const float* x0_re     = ptr[1];
    const float* x0_im     = ptr[2];
    const float* nu_log    = ptr[3];
    const float* theta_log = ptr[4];
    const float* gamma_log = ptr[5];
    const float* B_re      = ptr[6];
    const float* B_im      = ptr[7];
    const float* C_re      = ptr[8];
    const float* C_im      = ptr[9];
    const float* D         = ptr[10];
    float* out = (float*)d_out;

    static int attr_done = 0;
    if (!attr_done) {
        cudaFuncSetAttribute(k_merged, cudaFuncAttributeMaxDynamicSharedMemorySize, SMEM_BYTES);
        attr_done = 1;
    }

    k_lam<<<1, STATE>>>(nu_log, theta_log, gamma_log);
    int tot = 2 * STATE * IN_DIM + OUT_DIM * STATE;
    k_weights<<<(tot + 255) / 256, 256>>>(B_re, B_im, C_re, C_im);
    k_F<<<dim3(IN_DIM / 16, OUT_DIM / 16), dim3(16, 16)>>>(C_re, C_im, D);

    const long long Y_ELEMS      = (long long)NSEQ * OUT_DIM;   //  8,388,608
    const long long ST_C64_ELEMS = (long long)NSEQ * 2 * STATE; // 33,554,432
    long long cap = (long long)out_size;
    if (cap == Y_ELEMS / 2 + ST_C64_ELEMS / 2) cap *= 2;        // c64-counted case
    long long rem = cap - Y_ELEMS;

    if (rem >= ST_C64_ELEMS) {
        k_merged<<<NY_BLK, 512, SMEM_BYTES>>>(u, x0_re, x0_im, out, cap);
        k_gemm_c64<<<dim3(NSEQ / 128, (2 * STATE) / 64), 256>>>(
            u, IN_DIM, x0_re, x0_im, out + Y_ELEMS, rem);
    } else {
        k_merged<<<NY_BLK + NS_BLK, 512, SMEM_BYTES>>>(u, x0_re, x0_im, out, cap);
    }
}

// round 17
// speedup vs baseline: 1.1868x; 1.1862x over previous
#include <cuda_runtime.h>
#include <cuda_fp16.h>
#include <math.h>
#include <stdint.h>

#define IN_DIM   256
#define STATE    512
#define OUT_DIM  256
#define NSEQ     32768
#define KY       1280   // x0_re(512) | x0_im(512) | u(256)

// ---------------- device scratch (no allocation allowed), 16B-aligned ----------------
__device__ __align__(16) float g_lam_re[STATE];
__device__ __align__(16) float g_lam_im[STATE];
__device__ __align__(16) float g_gam[STATE];
__device__ __align__(16) float g_G[2 * STATE * IN_DIM];  // [1024,256] fp32 (k_F + c64 fallback)
// fp16 weights — ONLY referenced from device code (host shadow address invalid on ATS)
__device__ __align__(16) __half g_Wy_h[OUT_DIM * KY];     // [256][1280] = [P|Q|F]
__device__ __align__(16) __half g_Ws_h[STATE * IN_DIM];   // [512][256]  = Bn_re

// ---------------- PTX helpers (sm_80-era; legal on compute_103) ----------------
__device__ __forceinline__ uint32_t smem_u32(const void* p) {
    uint32_t a;
    asm("{ .reg .u64 t; cvta.to.shared.u64 t, %1; cvt.u32.u64 %0, t; }" : "=r"(a) : "l"(p));
    return a;
}
__device__ __forceinline__ void sts128(uint32_t a, uint32_t x, uint32_t y, uint32_t z, uint32_t w) {
    asm volatile("st.shared.v4.b32 [%0], {%1,%2,%3,%4};" :: "r"(a), "r"(x), "r"(y), "r"(z), "r"(w) : "memory");
}
__device__ __forceinline__ void cp16(uint32_t dst, const void* src) {
    asm volatile("cp.async.cg.shared.global [%0], [%1], 16;" :: "r"(dst), "l"(src) : "memory");
}
__device__ __forceinline__ void cp_commit_wait() {
    asm volatile("cp.async.commit_group;" ::: "memory");
    asm volatile("cp.async.wait_group 0;" ::: "memory");
}
__device__ __forceinline__ void ldm_x4(uint32_t* r, uint32_t addr) {
    asm volatile("ldmatrix.sync.aligned.m8n8.x4.shared.b16 {%0,%1,%2,%3}, [%4];"
        : "=r"(r[0]), "=r"(r[1]), "=r"(r[2]), "=r"(r[3]) : "r"(addr));
}
__device__ __forceinline__ void mma_f16(float* c, const uint32_t* a, const uint32_t* b) {
    asm volatile(
        "mma.sync.aligned.m16n8k16.row.col.f32.f16.f16.f32 "
        "{%0,%1,%2,%3}, {%4,%5,%6,%7}, {%8,%9}, {%0,%1,%2,%3};"
        : "+f"(c[0]), "+f"(c[1]), "+f"(c[2]), "+f"(c[3])
        : "r"(a[0]), "r"(a[1]), "r"(a[2]), "r"(a[3]), "r"(b[0]), "r"(b[1]));
}

// ---------------- precompute (3 launches) ----------------
__global__ void k_lam(const float* __restrict__ nu_log,
                      const float* __restrict__ theta_log,
                      const float* __restrict__ gamma_log) {
    int h = threadIdx.x;
    float mod = expf(-expf(nu_log[h]));
    float th  = expf(theta_log[h]);
    g_lam_re[h] = mod * cosf(th);
    g_lam_im[h] = mod * sinf(th);
    g_gam[h]    = expf(gamma_log[h]);
}

__global__ void k_weights(const float* __restrict__ B_re, const float* __restrict__ B_im,
                          const float* __restrict__ C_re, const float* __restrict__ C_im) {
    int idx = blockIdx.x * blockDim.x + threadIdx.x;
    const int NG = 2 * STATE * IN_DIM;
    const int NP = OUT_DIM * STATE;
    if (idx < NG) {
        int c = idx / IN_DIM, j = idx % IN_DIM, h = c >> 1;
        float b = (c & 1) ? B_im[h * IN_DIM + j] : B_re[h * IN_DIM + j];
        float v = b * g_gam[h];
        g_G[idx] = v;
        if (!(c & 1))
            g_Ws_h[h * IN_DIM + j] = __float2half(v);
    } else if (idx < NG + NP) {
        int t = idx - NG;
        int o = t / STATE, h = t % STATE;
        float cr = C_re[o * STATE + h], ci = C_im[o * STATE + h];
        float lr = g_lam_re[h], li = g_lam_im[h];
        g_Wy_h[o * KY + h]       = __float2half(lr * cr - li * ci);
        g_Wy_h[o * KY + 512 + h] = __float2half(-(li * cr + lr * ci));
    }
}

__global__ void k_F(const float* __restrict__ C_re, const float* __restrict__ C_im,
                    const float* __restrict__ D) {
    __shared__ float sCr[16][16], sCi[16][16], sGr[16][17], sGi[16][17];
    int o0 = blockIdx.y * 16, j0 = blockIdx.x * 16;
    int tx = threadIdx.x, ty = threadIdx.y;
    float acc = 0.f;
    for (int h0 = 0; h0 < STATE; h0 += 16) {
        sCr[ty][tx] = C_re[(o0 + ty) * STATE + h0 + tx];
        sCi[ty][tx] = C_im[(o0 + ty) * STATE + h0 + tx];
        sGr[ty][tx] = g_G[(2 * (h0 + ty)) * IN_DIM + j0 + tx];
        sGi[ty][tx] = g_G[(2 * (h0 + ty) + 1) * IN_DIM + j0 + tx];
        __syncthreads();
#pragma unroll
        for (int k = 0; k < 16; k++)
            acc += sCr[ty][k] * sGr[k][tx] - sCi[ty][k] * sGi[k][tx];
        __syncthreads();
    }
    float fv = D[(o0 + ty) * IN_DIM + j0 + tx] + acc;
    g_Wy_h[(o0 + ty) * KY + 1024 + j0 + tx] = __float2half(fv);
}

// ---------------- merged pipelined mma.sync GEMM (fp16 A + fp16 W, no split) ----------------
// BM=128, BN=128, BK=64, 512 thr (16 warps), 1 CTA/SM. N-inner block map (L2 reuse of A).
//   y blocks   [0, 512):    m = t>>1, n = t&1   (K=1280)
//   s blocks   [512, 1536): m = t>>2, n = t&3   (K=256, epilogue Re(lam*x0), clamped)
// Warps: 4 over M x 4 over N, warp tile 32x32 (mt=2, nt=4), 1 MMA per (mt,nt) per k16.
// Smem row stride 144 B (64 halves + 16B pad): row step = 36 words ≡ 4 mod 32 -> ldmatrix
// 8-row addresses hit 8 distinct 16B bank groups (conflict-free).
#define NY_BLK 512
#define NS_BLK 1024
#define ROWB   144
#define A_B    0
#define W_B    (128 * ROWB)          // 18432
#define STG_B  (2 * 128 * ROWB)      // 36864
#define SMEM_BYTES (2 * STG_B)       // 73728

__global__ __launch_bounds__(512, 1)
void k_merged(const float* __restrict__ u, const float* __restrict__ x0_re,
              const float* __restrict__ x0_im, float* __restrict__ out, long long lim) {
    extern __shared__ __half sm[];
    uint32_t sb = smem_u32(sm);

    int bid = blockIdx.x;
    bool is_y = bid < NY_BLK;
    int t_ = is_y ? bid : bid - NY_BLK;
    int m0, n0;
    if (is_y) { m0 = (t_ >> 1) * 128; n0 = (t_ & 1) * 128; }
    else      { m0 = (t_ >> 2) * 128; n0 = (t_ & 3) * 128; }
    int KT = is_y ? KY : IN_DIM;
    const __half* __restrict__ Wp = is_y ? g_Wy_h : g_Ws_h;

    int tid  = threadIdx.x;
    int wid  = tid >> 5;
    int lane = tid & 31;
    int wm = wid & 3;          // 4 warps over M (32 rows each)
    int wn = wid >> 2;         // 4 warps over N (32 cols each)

    float acc[2][4][4];
#pragma unroll
    for (int i = 0; i < 2; i++)
#pragma unroll
        for (int j = 0; j < 4; j++)
#pragma unroll
            for (int q = 0; q < 4; q++) acc[i][j][q] = 0.f;

    int lr_ = tid >> 2;         // loader row (0..127) for BOTH A and W
    int lq  = tid & 3;          // 16-element k-chunk within 64
    uint32_t lbase = (uint32_t)lr_ * ROWB + lq * 32;

    auto a_ptr = [&](int k0) -> const float* {
        const float* Ag; int astr;
        if (is_y) {
            if (k0 < 512)       { Ag = x0_re + k0;          astr = STATE; }
            else if (k0 < 1024) { Ag = x0_im + (k0 - 512);  astr = STATE; }
            else                { Ag = u + (k0 - 1024);     astr = IN_DIM; }
        } else { Ag = u + k0; astr = IN_DIM; }
        return Ag + (size_t)(m0 + lr_) * astr + lq * 16;
    };

    float4 pv0, pv1, pv2, pv3;  // 16 fp32 A prefetch values per thread
    auto load_a = [&](int k0) {
        const float* p = a_ptr(k0);
        pv0 = *(const float4*)(p);
        pv1 = *(const float4*)(p + 4);
        pv2 = *(const float4*)(p + 8);
        pv3 = *(const float4*)(p + 12);
    };
    auto issue_w = [&](int k0, uint32_t stgB) {
        size_t off = (size_t)(n0 + lr_) * KT + k0 + lq * 16;
        uint32_t b = sb + stgB + W_B + lbase;
        cp16(b,      Wp + off);
        cp16(b + 16, Wp + off + 8);
    };
    auto store_a = [&](uint32_t stgB) {
        float xs[16] = {pv0.x, pv0.y, pv0.z, pv0.w, pv1.x, pv1.y, pv1.z, pv1.w,
                        pv2.x, pv2.y, pv2.z, pv2.w, pv3.x, pv3.y, pv3.z, pv3.w};
        uint32_t hu[8];
#pragma unroll
        for (int q = 0; q < 8; q++) {
            __half h0 = __float2half(xs[2 * q]);
            __half h1 = __float2half(xs[2 * q + 1]);
            hu[q] = (uint32_t)__half_as_ushort(h0) | ((uint32_t)__half_as_ushort(h1) << 16);
        }
        uint32_t b = sb + stgB + A_B + lbase;
        sts128(b,      hu[0], hu[1], hu[2], hu[3]);
        sts128(b + 16, hu[4], hu[5], hu[6], hu[7]);
    };

    // prologue
    load_a(0);
    issue_w(0, 0);
    store_a(0);
    cp_commit_wait();
    __syncthreads();

#pragma unroll 1
    for (int k0 = 0; k0 < KT; k0 += 64) {
        uint32_t cur = (uint32_t)((k0 >> 6) & 1) * STG_B;
        uint32_t nxt = STG_B - cur;
        bool more = (k0 + 64) < KT;
        if (more) { load_a(k0 + 64); issue_w(k0 + 64, nxt); }

        uint32_t sc = sb + cur;
#pragma unroll
        for (int ks = 0; ks < 4; ks++) {
            uint32_t ah[2][4], bh[4][2];
            uint32_t acol = ks * 32 + (lane >> 4) * 16;
#pragma unroll
            for (int mt = 0; mt < 2; mt++) {
                uint32_t r = wm * 32 + mt * 16 + (lane & 15);
                ldm_x4(ah[mt], sc + A_B + r * ROWB + acol);
            }
            // W fragments: paired x4 — one call covers two n-subtiles (16 rows x 16 k)
            uint32_t brow_lo = (uint32_t)((lane >> 4) << 3) + (lane & 7);
            uint32_t bcol    = ks * 32 + ((lane >> 3) & 1) * 16;
#pragma unroll
            for (int p = 0; p < 2; p++) {
                uint32_t n = wn * 32 + p * 16 + brow_lo;
                uint32_t th[4];
                ldm_x4(th, sc + W_B + n * ROWB + bcol);
                bh[2*p][0] = th[0]; bh[2*p][1] = th[1];
                bh[2*p+1][0] = th[2]; bh[2*p+1][1] = th[3];
            }
#pragma unroll
            for (int mt = 0; mt < 2; mt++)
#pragma unroll
                for (int nt = 0; nt < 4; nt++)
                    mma_f16(acc[mt][nt], ah[mt], bh[nt]);
        }

        if (more) { store_a(nxt); cp_commit_wait(); }
        __syncthreads();
    }

    // epilogue
    int rbase = m0 + wm * 32 + (lane >> 2);
    int cbase = n0 + wn * 32 + 2 * (lane & 3);
#pragma unroll
    for (int mt = 0; mt < 2; mt++) {
#pragma unroll
        for (int nt = 0; nt < 4; nt++) {
            int col = cbase + nt * 8;
#pragma unroll
            for (int hrow = 0; hrow < 2; hrow++) {
                int row = rbase + mt * 16 + hrow * 8;
                float v0 = acc[mt][nt][2 * hrow];
                float v1 = acc[mt][nt][2 * hrow + 1];
                if (is_y) {
                    *(float2*)(out + (size_t)row * OUT_DIM + col) = make_float2(v0, v1);
                } else {
                    long long idx = (long long)NSEQ * OUT_DIM + (long long)row * STATE + col;
                    if (idx + 1 < lim) {
                        float2 lr2 = *(const float2*)&g_lam_re[col];
                        float2 li2 = *(const float2*)&g_lam_im[col];
                        float2 xr  = *(const float2*)&x0_re[(size_t)row * STATE + col];
                        float2 xi  = *(const float2*)&x0_im[(size_t)row * STATE + col];
                        float2 o2;
                        o2.x = lr2.x * xr.x - li2.x * xi.x + v0;
                        o2.y = lr2.y * xr.y - li2.y * xi.y + v1;
                        *(float2*)(out + idx) = o2;
                    }
                }
            }
        }
    }
}

// ---------------- legacy fp32 GEMM (interleaved-c64 state fallback only) ----------------
__global__ __launch_bounds__(256)
void k_gemm_c64(const float* __restrict__ A0, int K0,
                const float* __restrict__ x0_re, const float* __restrict__ x0_im,
                float* __restrict__ out, long long lim) {
    const int BM = 128, BN = 64, BK = 16;
    __shared__ float As[BK][BM + 4];
    __shared__ float Bs[BK][BN + 4];
    int tid = threadIdx.x;
    int m0 = blockIdx.x * BM;
    int n0 = blockIdx.y * BN;
    int tx = tid & 15, ty = tid >> 4;
    float acc[8][4];
#pragma unroll
    for (int i = 0; i < 8; i++)
#pragma unroll
        for (int j = 0; j < 4; j++) acc[i][j] = 0.f;
#pragma unroll 1
    for (int k0 = 0; k0 < K0; k0 += BK) {
#pragma unroll
        for (int l = 0; l < 2; l++) {
            int f = tid + l * 256;
            int r = f >> 2, kk4 = (f & 3) * 4;
            float4 v = *(const float4*)&A0[(size_t)(m0 + r) * K0 + k0 + kk4];
            As[kk4 + 0][r] = v.x; As[kk4 + 1][r] = v.y;
            As[kk4 + 2][r] = v.z; As[kk4 + 3][r] = v.w;
        }
        {
            int n = tid >> 2, kk4 = (tid & 3) * 4;
            float4 v = *(const float4*)&g_G[(size_t)(n0 + n) * K0 + k0 + kk4];
            Bs[kk4 + 0][n] = v.x; Bs[kk4 + 1][n] = v.y;
            Bs[kk4 + 2][n] = v.z; Bs[kk4 + 3][n] = v.w;
        }
        __syncthreads();
#pragma unroll
        for (int kk = 0; kk < BK; kk++) {
            float4 b  = *(const float4*)&Bs[kk][tx * 4];
            float4 a0 = *(const float4*)&As[kk][ty * 8];
            float4 a1 = *(const float4*)&As[kk][ty * 8 + 4];
            float av[8] = {a0.x, a0.y, a0.z, a0.w, a1.x, a1.y, a1.z, a1.w};
            float bv[4] = {b.x, b.y, b.z, b.w};
#pragma unroll
            for (int i = 0; i < 8; i++)
#pragma unroll
                for (int j = 0; j < 4; j++) acc[i][j] += av[i] * bv[j];
        }
        __syncthreads();
    }
    int c0 = n0 + tx * 4;
    int h0 = c0 >> 1;
    float lr0 = g_lam_re[h0],     li0 = g_lam_im[h0];
    float lr1 = g_lam_re[h0 + 1], li1 = g_lam_im[h0 + 1];
#pragma unroll
    for (int i = 0; i < 8; i++) {
        int row = m0 + ty * 8 + i;
        long long idx = (long long)row * (2 * STATE) + c0;
        if (idx + 3 < lim) {
            float xr0 = x0_re[(size_t)row * STATE + h0];
            float xi0 = x0_im[(size_t)row * STATE + h0];
            float xr1 = x0_re[(size_t)row * STATE + h0 + 1];
            float xi1 = x0_im[(size_t)row * STATE + h0 + 1];
            float4 v;
            v.x = lr0 * xr0 - li0 * xi0 + acc[i][0];
            v.y = lr0 * xi0 + li0 * xr0 + acc[i][1];
            v.z = lr1 * xr1 - li1 * xi1 + acc[i][2];
            v.w = lr1 * xi1 + li1 * xr1 + acc[i][3];
            *(float4*)&out[idx] = v;
        }
    }
}

// ---------------- launch ----------------
extern "C" void kernel_launch(void* const* d_in, const int* in_sizes, int n_in,
                              void* d_out, int out_size) {
    const long long expect[11] = {
        (long long)NSEQ * IN_DIM, (long long)NSEQ * STATE, (long long)NSEQ * STATE,
        STATE, STATE, STATE,
        (long long)STATE * IN_DIM, (long long)STATE * IN_DIM,
        (long long)OUT_DIM * STATE, (long long)OUT_DIM * STATE,
        (long long)OUT_DIM * IN_DIM
    };
    const float* ptr[11];
    bool used[32] = {false};
    for (int e = 0; e < 11; e++) {
        ptr[e] = nullptr;
        for (int i = 0; i < n_in; i++) {
            if (!used[i] && (long long)in_sizes[i] == expect[e]) {
                ptr[e] = (const float*)d_in[i];
                used[i] = true;
                break;
            }
        }
        if (!ptr[e]) ptr[e] = (const float*)d_in[e < n_in ? e : 0];
    }
    const float* u         = ptr[0];
    const float* x0_re     = ptr[1];
    const float* x0_im     = ptr[2];
    const float* nu_log    = ptr[3];
    const float* theta_log = ptr[4];
    const float* gamma_log = ptr[5];
    const float* B_re      = ptr[6];
    const float* B_im      = ptr[7];
    const float* C_re      = ptr[8];
    const float* C_im      = ptr[9];
    const float* D         = ptr[10];
    float* out = (float*)d_out;

    static int attr_done = 0;
    if (!attr_done) {
        cudaFuncSetAttribute(k_merged, cudaFuncAttributeMaxDynamicSharedMemorySize, SMEM_BYTES);
        attr_done = 1;
    }

    k_lam<<<1, STATE>>>(nu_log, theta_log, gamma_log);
    int tot = 2 * STATE * IN_DIM + OUT_DIM * STATE;
    k_weights<<<(tot + 255) / 256, 256>>>(B_re, B_im, C_re, C_im);
    k_F<<<dim3(IN_DIM / 16, OUT_DIM / 16), dim3(16, 16)>>>(C_re, C_im, D);

    const long long Y_ELEMS      = (long long)NSEQ * OUT_DIM;   //  8,388,608
    const long long ST_C64_ELEMS = (long long)NSEQ * 2 * STATE; // 33,554,432
    long long cap = (long long)out_size;
    if (cap == Y_ELEMS / 2 + ST_C64_ELEMS / 2) cap *= 2;        // c64-counted case
    long long rem = cap - Y_ELEMS;

    if (rem >= ST_C64_ELEMS) {
        k_merged<<<NY_BLK, 512, SMEM_BYTES>>>(u, x0_re, x0_im, out, cap);
        k_gemm_c64<<<dim3(NSEQ / 128, (2 * STATE) / 64), 256>>>(
            u, IN_DIM, x0_re, x0_im, out + Y_ELEMS, rem);
    } else {
        k_merged<<<NY_BLK + NS_BLK, 512, SMEM_BYTES>>>(u, x0_re, x0_im, out, cap);
    }
}